// round 9
// baseline (speedup 1.0000x reference)
#include <cuda_runtime.h>
#include <cuda_bf16.h>

#define TOK   8192
#define SEQ   2048
#define BATCH 4
#define DIM   768
#define NHEAD 12
#define HDIM  64
#define BH    (BATCH*NHEAD)
#define HID   3072
#define QKSCALE 0.125f
#define LN_EPS 1e-5f

// -------- scratch --------
__device__ float g_h[TOK * DIM];
__device__ float g_q[BH * SEQ * HDIM];
__device__ float g_k[BH * SEQ * HDIM];
__device__ float g_v[BH * SEQ * HDIM];
__device__ float g_attnout[TOK * DIM];
__device__ float g_x1[TOK * DIM];
__device__ float g_u[TOK * HID];
__device__ float g_qkvT[3 * DIM * DIM];
__device__ float g_projT[DIM * DIM];
__device__ float g_fc1T[HID * DIM];
__device__ float g_fc2T[DIM * HID];

// ---------- helpers ----------
__device__ __forceinline__ void mma_tf32(float& d0, float& d1, float& d2, float& d3,
                                         unsigned a0, unsigned a1, unsigned a2, unsigned a3,
                                         unsigned b0, unsigned b1)
{
    asm volatile(
        "mma.sync.aligned.m16n8k8.row.col.f32.tf32.tf32.f32 "
        "{%0,%1,%2,%3},{%4,%5,%6,%7},{%8,%9},{%0,%1,%2,%3};"
        : "+f"(d0), "+f"(d1), "+f"(d2), "+f"(d3)
        : "r"(a0), "r"(a1), "r"(a2), "r"(a3), "r"(b0), "r"(b1));
}

__device__ __forceinline__ void ldsm4(unsigned& r0, unsigned& r1, unsigned& r2, unsigned& r3,
                                      unsigned addr)
{
    asm volatile("ldmatrix.sync.aligned.m8n8.x4.shared.b16 {%0,%1,%2,%3}, [%4];"
        : "=r"(r0), "=r"(r1), "=r"(r2), "=r"(r3) : "r"(addr));
}

__device__ __forceinline__ void cp16(unsigned saddr, const void* gptr) {
    asm volatile("cp.async.cg.shared.global [%0], [%1], 16;" :: "r"(saddr), "l"(gptr));
}
#define CP_COMMIT() asm volatile("cp.async.commit_group;")
#define CP_WAIT(n)  asm volatile("cp.async.wait_group %0;" :: "n"(n))
#define BAR_PAIR(id) asm volatile("bar.sync %0, 64;" :: "r"(id) : "memory")

// ============================ LayerNorm ============================
__global__ __launch_bounds__(192) void ln_kernel(
    const float* __restrict__ x, const float* __restrict__ gamma,
    const float* __restrict__ beta, float* __restrict__ out)
{
    int row = blockIdx.x;
    int tid = threadIdx.x;
    const float* xr = x + (size_t)row * DIM;
    float4 v = *(const float4*)(xr + tid * 4);
    float s  = v.x + v.y + v.z + v.w;
    float s2 = v.x * v.x + v.y * v.y + v.z * v.z + v.w * v.w;
    #pragma unroll
    for (int o = 16; o; o >>= 1) {
        s  += __shfl_xor_sync(0xffffffffu, s,  o);
        s2 += __shfl_xor_sync(0xffffffffu, s2, o);
    }
    __shared__ float rs[6], rs2[6];
    int lane = tid & 31, wid = tid >> 5;
    if (lane == 0) { rs[wid] = s; rs2[wid] = s2; }
    __syncthreads();
    float ts = 0.f, ts2 = 0.f;
    #pragma unroll
    for (int i = 0; i < 6; i++) { ts += rs[i]; ts2 += rs2[i]; }
    float mean = ts * (1.0f / DIM);
    float var  = ts2 * (1.0f / DIM) - mean * mean;
    float inv  = rsqrtf(var + LN_EPS);
    float4 g = *(const float4*)(gamma + tid * 4);
    float4 b = *(const float4*)(beta + tid * 4);
    float4 o;
    o.x = (v.x - mean) * inv * g.x + b.x;
    o.y = (v.y - mean) * inv * g.y + b.y;
    o.z = (v.z - mean) * inv * g.z + b.z;
    o.w = (v.w - mean) * inv * g.w + b.w;
    *(float4*)(out + (size_t)row * DIM + tid * 4) = o;
}

// ============================ Weight transpose: in[K,N] -> out[N,K] ============================
__global__ __launch_bounds__(256) void transpose_k(
    const float* __restrict__ in, float* __restrict__ out, int K, int N)
{
    __shared__ float t[32][33];
    int n0 = blockIdx.x * 32, k0 = blockIdx.y * 32;
    int tx = threadIdx.x, ty = threadIdx.y;
    #pragma unroll
    for (int i = ty; i < 32; i += 8)
        t[i][tx] = in[(size_t)(k0 + i) * N + n0 + tx];
    __syncthreads();
    #pragma unroll
    for (int i = ty; i < 32; i += 8)
        out[(size_t)(n0 + i) * K + k0 + tx] = t[tx][i];
}

// ============================ TF32 GEMM 128x256, warp 64x64, 4-stage cp.async ============================
// A[M,K] row-major; WT[N,K] row-major (i.e. W^T). Both smem tiles are [rows][36] padded.
#define TW 36
#define A_WORDS (128 * TW)                 // 4608
#define B_WORDS (256 * TW)                 // 9216
#define STAGE_WORDS (A_WORDS + B_WORDS)    // 13824
#define NSTAGE 4
#define GEMM_SMEM (NSTAGE * STAGE_WORDS * 4)   // 221184

__device__ __forceinline__ void load_chunk(
    unsigned sb, const float* Ag, const float* Bg, int K, int tid)
{
    #pragma unroll
    for (int i = 0; i < 4; i++) {              // A: 128 rows x 32 floats
        int idx = tid + i * 256;
        int r = idx >> 3, g = idx & 7;
        cp16(sb + (r * TW + g * 4) * 4, Ag + (size_t)r * K + g * 4);
    }
    #pragma unroll
    for (int i = 0; i < 8; i++) {              // B: 256 rows x 32 floats
        int idx = tid + i * 256;
        int r = idx >> 3, g = idx & 7;
        cp16(sb + (A_WORDS + r * TW + g * 4) * 4, Bg + (size_t)r * K + g * 4);
    }
}

template <int EPI>
__global__ __launch_bounds__(256) void mma_gemm(
    const float* __restrict__ A, const float* __restrict__ WT,
    const float* __restrict__ bias, const float* __restrict__ res,
    float* __restrict__ C, int M, int N, int K,
    float* __restrict__ qo, float* __restrict__ ko, float* __restrict__ vo,
    const float* __restrict__ c0, const float* __restrict__ c1,
    const float* __restrict__ c2)
{
    extern __shared__ unsigned smem[];

    const int tid  = threadIdx.x;
    const int lane = tid & 31;
    const int w    = tid >> 5;
    const int wm   = w >> 2;            // 0..1 : 64-row half
    const int wn   = w & 3;             // 0..3 : 64-col quarter
    const int bx = blockIdx.x, by = blockIdx.y;

    const float* Ag = A  + (size_t)(by * 128) * K;
    const float* Bg = WT + (size_t)(bx * 256) * K;

    const unsigned sbase = (unsigned)__cvta_generic_to_shared(smem);
    const int nch = K >> 5;

    // prologue: stages 0..2
    #pragma unroll
    for (int t = 0; t < 3; t++) {
        load_chunk(sbase + t * STAGE_WORDS * 4, Ag + t * 32, Bg + t * 32, K, tid);
        CP_COMMIT();
    }

    float acc[4][8][4];
    #pragma unroll
    for (int i = 0; i < 4; i++)
        #pragma unroll
        for (int j = 0; j < 8; j++)
            #pragma unroll
            for (int r = 0; r < 4; r++) acc[i][j][r] = 0.f;

    const unsigned a_laneoff = (((lane & 7) + ((lane >> 3) & 1) * 8) * TW + (lane >> 4) * 4) * 4;
    const unsigned b_laneoff = (((lane & 7) + ((lane >> 4) & 1) * 8) * TW + ((lane >> 3) & 1) * 4) * 4;

    for (int t = 0; t < nch; t++) {
        CP_WAIT(2);
        __syncthreads();
        // prefetch t+3 (stage (t+3)%4 == (t-1)%4, safe: all warps passed iter t-1)
        if (t + 3 < nch)
            load_chunk(sbase + ((t + 3) & 3) * STAGE_WORDS * 4,
                       Ag + (t + 3) * 32, Bg + (t + 3) * 32, K, tid);
        CP_COMMIT();

        const unsigned sA = sbase + (t & 3) * STAGE_WORDS * 4;
        const unsigned sB = sA + A_WORDS * 4;
        #pragma unroll
        for (int kk = 0; kk < 32; kk += 8) {
            unsigned af[4][4], bf[8][2];
            #pragma unroll
            for (int mt = 0; mt < 4; mt++) {
                unsigned addr = sA + ((wm * 64 + mt * 16) * TW + kk) * 4 + a_laneoff;
                ldsm4(af[mt][0], af[mt][1], af[mt][2], af[mt][3], addr);
            }
            #pragma unroll
            for (int p = 0; p < 4; p++) {
                unsigned addr = sB + ((wn * 64 + p * 16) * TW + kk) * 4 + b_laneoff;
                ldsm4(bf[2 * p][0], bf[2 * p][1], bf[2 * p + 1][0], bf[2 * p + 1][1], addr);
            }
            #pragma unroll
            for (int mt = 0; mt < 4; mt++)
                #pragma unroll
                for (int nt = 0; nt < 8; nt++)
                    mma_tf32(acc[mt][nt][0], acc[mt][nt][1], acc[mt][nt][2], acc[mt][nt][3],
                             af[mt][0], af[mt][1], af[mt][2], af[mt][3],
                             bf[nt][0], bf[nt][1]);
        }
    }

    float ga = 0.f, gb = 0.f, gc = 0.f;
    if (EPI == 3) { ga = *c0; gb = *c1; gc = *c2; }

    #pragma unroll
    for (int mt = 0; mt < 4; mt++) {
        #pragma unroll
        for (int nt = 0; nt < 8; nt++) {
            int r0  = by * 128 + wm * 64 + mt * 16 + (lane >> 2);
            int cc0 = bx * 256 + wn * 64 + nt * 8 + 2 * (lane & 3);
            #pragma unroll
            for (int half = 0; half < 2; half++) {
                int r = r0 + half * 8;
                float v0 = acc[mt][nt][half * 2 + 0] + bias[cc0];
                float v1 = acc[mt][nt][half * 2 + 1] + bias[cc0 + 1];
                if (EPI == 1) {
                    int which = cc0 / DIM;
                    int jj = cc0 - which * DIM;
                    int h = jj >> 6, d = jj & 63;
                    int b = r >> 11, n = r & 2047;
                    float* dst = (which == 0) ? qo : (which == 1) ? ko : vo;
                    if (which == 0) { v0 *= QKSCALE; v1 *= QKSCALE; }
                    size_t base = (((size_t)(b * NHEAD + h) * SEQ) + n) * HDIM + d;
                    dst[base] = v0; dst[base + 1] = v1;
                } else if (EPI == 2) {
                    size_t base = (size_t)r * N + cc0;
                    C[base]     = v0 + res[base];
                    C[base + 1] = v1 + res[base + 1];
                } else if (EPI == 3) {
                    size_t base = (size_t)r * N + cc0;
                    C[base]     = fmaf(v0, fmaf(ga, v0, gb), gc);
                    C[base + 1] = fmaf(v1, fmaf(ga, v1, gb), gc);
                } else {
                    size_t base = (size_t)r * N + cc0;
                    C[base] = v0; C[base + 1] = v1;
                }
            }
        }
    }
}

// ============================ Polynomial attention (round-5, proven) ============================
#define KS_W 68
#define VS_W 72
#define KS_T (64 * KS_W)
#define VS_T (64 * VS_W)
#define ATTN_SMEM ((2 * KS_T + 2 * VS_T + 64 * 68) * 4)

__global__ __launch_bounds__(256, 2) void attn_mma(
    const float* __restrict__ Q, const float* __restrict__ Kg,
    const float* __restrict__ Vg, float* __restrict__ out,
    const float* __restrict__ pa, const float* __restrict__ pb,
    const float* __restrict__ pc)
{
    extern __shared__ unsigned dsm[];
    unsigned* Ks = dsm;
    unsigned* Vs = dsm + 2 * KS_T;
    unsigned* Ss = dsm + 2 * KS_T + 2 * VS_T;
    __shared__ float rsums[64];

    const int tid  = threadIdx.x;
    const int lane = tid & 31;
    const int w    = tid >> 5;
    const int mt   = w >> 1;
    const int nh   = w & 1;
    const int bh   = blockIdx.y;
    const int n0   = blockIdx.x * 64;

    const float* Qb = Q  + (size_t)bh * SEQ * HDIM;
    const float* Kb = Kg + (size_t)bh * SEQ * HDIM;
    const float* Vb = Vg + (size_t)bh * SEQ * HDIM;

    const float aa = *pa, bb = *pb, cc = *pc;

    if (tid < 64) rsums[tid] = 0.f;

    const int grow = tid >> 4;
    const int gc4  = tid & 15;

    const unsigned sKs = (unsigned)__cvta_generic_to_shared(Ks);
    const unsigned sVs = (unsigned)__cvta_generic_to_shared(Vs);
    const unsigned sSs = (unsigned)__cvta_generic_to_shared(Ss);

    #pragma unroll
    for (int it = 0; it < 4; it++) {
        int r = it * 16 + grow;
        cp16(sSs + (r * 68 + gc4 * 4) * 4, Qb + (size_t)(n0 + r) * HDIM + gc4 * 4);
    }
    CP_COMMIT();
    #pragma unroll
    for (int t = 0; t < 2; t++) {
        #pragma unroll
        for (int it = 0; it < 4; it++) {
            int r = it * 16 + grow;
            cp16(sKs + (t * KS_T + r * KS_W + gc4 * 4) * 4,
                 Kb + (size_t)(t * 64 + r) * HDIM + gc4 * 4);
            cp16(sVs + (t * VS_T + r * VS_W + gc4 * 4) * 4,
                 Vb + (size_t)(t * 64 + r) * HDIM + gc4 * 4);
        }
        CP_COMMIT();
    }
    CP_WAIT(2);
    __syncthreads();

    const unsigned a_laneoff = (((lane & 7) + ((lane >> 3) & 1) * 8) * 68 + (lane >> 4) * 4) * 4;
    const unsigned b_laneoff = (((lane & 7) + ((lane >> 4) & 1) * 8) * KS_W + ((lane >> 3) & 1) * 4) * 4;

    unsigned qf[8][4];
    #pragma unroll
    for (int kk = 0; kk < 8; kk++) {
        unsigned addr = sSs + (mt * 16 * 68 + kk * 8) * 4 + a_laneoff;
        ldsm4(qf[kk][0], qf[kk][1], qf[kk][2], qf[kk][3], addr);
    }

    float oacc[4][4];
    #pragma unroll
    for (int ntt = 0; ntt < 4; ntt++)
        #pragma unroll
        for (int r = 0; r < 4; r++) oacc[ntt][r] = 0.f;
    float rs0 = 0.f, rs1 = 0.f;

    for (int m = 0; m < 32; m++) {
        const int buf = m & 1;
        CP_WAIT(1);
        __syncthreads();

        float sacc[4][4];
        #pragma unroll
        for (int ntt = 0; ntt < 4; ntt++)
            #pragma unroll
            for (int r = 0; r < 4; r++) sacc[ntt][r] = 0.f;

        unsigned kbase = sKs + buf * KS_T * 4;
        #pragma unroll
        for (int kk = 0; kk < 8; kk++) {
            unsigned bf[4][2];
            #pragma unroll
            for (int p = 0; p < 2; p++) {
                unsigned addr = kbase + ((nh * 32 + p * 16) * KS_W + kk * 8) * 4 + b_laneoff;
                ldsm4(bf[2 * p][0], bf[2 * p][1], bf[2 * p + 1][0], bf[2 * p + 1][1], addr);
            }
            #pragma unroll
            for (int ntt = 0; ntt < 4; ntt++)
                mma_tf32(sacc[ntt][0], sacc[ntt][1], sacc[ntt][2], sacc[ntt][3],
                         qf[kk][0], qf[kk][1], qf[kk][2], qf[kk][3],
                         bf[ntt][0], bf[ntt][1]);
        }

        #pragma unroll
        for (int ntt = 0; ntt < 4; ntt++) {
            #pragma unroll
            for (int r = 0; r < 4; r++) {
                float t = sacc[ntt][r];
                t = fmaf(t, fmaf(aa, t, bb), cc);
                t = fmaxf(t, 1e-6f);
                sacc[ntt][r] = t;
                if (r < 2) rs0 += t; else rs1 += t;
            }
        }

        #pragma unroll
        for (int ntt = 0; ntt < 4; ntt++) {
            int row = mt * 16 + (lane >> 2);
            int col = nh * 32 + ntt * 8 + 2 * (lane & 3);
            uint2 u0 = make_uint2(__float_as_uint(sacc[ntt][0]), __float_as_uint(sacc[ntt][1]));
            uint2 u1 = make_uint2(__float_as_uint(sacc[ntt][2]), __float_as_uint(sacc[ntt][3]));
            *(uint2*)&Ss[row * 68 + col]       = u0;
            *(uint2*)&Ss[(row + 8) * 68 + col] = u1;
        }
        BAR_PAIR(1 + mt);

        const unsigned* Vbuf = Vs + buf * VS_T;
        #pragma unroll
        for (int kk = 0; kk < 8; kk++) {
            unsigned af[4];
            unsigned addr = sSs + (mt * 16 * 68 + kk * 8) * 4 + a_laneoff;
            ldsm4(af[0], af[1], af[2], af[3], addr);
            unsigned bfv[4][2];
            #pragma unroll
            for (int ntt = 0; ntt < 4; ntt++) {
                int dcol = nh * 32 + ntt * 8 + (lane >> 2);
                bfv[ntt][0] = Vbuf[(kk * 8 + (lane & 3)) * VS_W + dcol];
                bfv[ntt][1] = Vbuf[(kk * 8 + (lane & 3) + 4) * VS_W + dcol];
            }
            #pragma unroll
            for (int ntt = 0; ntt < 4; ntt++)
                mma_tf32(oacc[ntt][0], oacc[ntt][1], oacc[ntt][2], oacc[ntt][3],
                         af[0], af[1], af[2], af[3],
                         bfv[ntt][0], bfv[ntt][1]);
        }
        __syncthreads();

        if (m + 2 < 32) {
            int tt = m + 2;
            #pragma unroll
            for (int it = 0; it < 4; it++) {
                int r = it * 16 + grow;
                cp16(sKs + (buf * KS_T + r * KS_W + gc4 * 4) * 4,
                     Kb + (size_t)(tt * 64 + r) * HDIM + gc4 * 4);
                cp16(sVs + (buf * VS_T + r * VS_W + gc4 * 4) * 4,
                     Vb + (size_t)(tt * 64 + r) * HDIM + gc4 * 4);
            }
        }
        CP_COMMIT();
    }

    rs0 += __shfl_xor_sync(0xffffffffu, rs0, 1);
    rs0 += __shfl_xor_sync(0xffffffffu, rs0, 2);
    rs1 += __shfl_xor_sync(0xffffffffu, rs1, 1);
    rs1 += __shfl_xor_sync(0xffffffffu, rs1, 2);
    if ((lane & 3) == 0) {
        atomicAdd(&rsums[mt * 16 + (lane >> 2)], rs0);
        atomicAdd(&rsums[mt * 16 + (lane >> 2) + 8], rs1);
    }
    __syncthreads();

    int b = bh / NHEAD, h = bh % NHEAD;
    int row0 = mt * 16 + (lane >> 2);
    float inv0 = 1.0f / (rsums[row0] + 1e-8f);
    float inv1 = 1.0f / (rsums[row0 + 8] + 1e-8f);
    #pragma unroll
    for (int ntt = 0; ntt < 4; ntt++) {
        int d = nh * 32 + ntt * 8 + 2 * (lane & 3);
        size_t base0 = ((size_t)(b * SEQ + n0 + row0)) * DIM + h * HDIM + d;
        size_t base1 = ((size_t)(b * SEQ + n0 + row0 + 8)) * DIM + h * HDIM + d;
        out[base0]     = oacc[ntt][0] * inv0;
        out[base0 + 1] = oacc[ntt][1] * inv0;
        out[base1]     = oacc[ntt][2] * inv1;
        out[base1 + 1] = oacc[ntt][3] * inv1;
    }
}

// ============================ launch ============================
extern "C" void kernel_launch(void* const* d_in, const int* in_sizes, int n_in,
                              void* d_out, int out_size)
{
    const float* x      = (const float*)d_in[0];
    const float* ln1_g  = (const float*)d_in[1];
    const float* ln1_b  = (const float*)d_in[2];
    const float* ln2_g  = (const float*)d_in[3];
    const float* ln2_b  = (const float*)d_in[4];
    const float* qkv_w  = (const float*)d_in[5];
    const float* qkv_b  = (const float*)d_in[6];
    const float* proj_w = (const float*)d_in[7];
    const float* proj_b = (const float*)d_in[8];
    const float* fc1_w  = (const float*)d_in[9];
    const float* fc1_b  = (const float*)d_in[10];
    const float* fc2_w  = (const float*)d_in[11];
    const float* fc2_b  = (const float*)d_in[12];
    const float* attn_a = (const float*)d_in[13];
    const float* attn_b = (const float*)d_in[14];
    const float* attn_c = (const float*)d_in[15];
    const float* gelu_a = (const float*)d_in[16];
    const float* gelu_b = (const float*)d_in[17];
    const float* gelu_c = (const float*)d_in[18];
    float* out = (float*)d_out;

    void *p_h, *p_q, *p_k, *p_v, *p_ao, *p_x1, *p_u;
    void *p_qkvT, *p_projT, *p_fc1T, *p_fc2T;
    cudaGetSymbolAddress(&p_h,  g_h);
    cudaGetSymbolAddress(&p_q,  g_q);
    cudaGetSymbolAddress(&p_k,  g_k);
    cudaGetSymbolAddress(&p_v,  g_v);
    cudaGetSymbolAddress(&p_ao, g_attnout);
    cudaGetSymbolAddress(&p_x1, g_x1);
    cudaGetSymbolAddress(&p_u,  g_u);
    cudaGetSymbolAddress(&p_qkvT, g_qkvT);
    cudaGetSymbolAddress(&p_projT, g_projT);
    cudaGetSymbolAddress(&p_fc1T, g_fc1T);
    cudaGetSymbolAddress(&p_fc2T, g_fc2T);
    float* h_  = (float*)p_h;
    float* q_  = (float*)p_q;
    float* k_  = (float*)p_k;
    float* v_  = (float*)p_v;
    float* ao_ = (float*)p_ao;
    float* x1_ = (float*)p_x1;
    float* u_  = (float*)p_u;
    float* qkvT_ = (float*)p_qkvT;
    float* projT_ = (float*)p_projT;
    float* fc1T_ = (float*)p_fc1T;
    float* fc2T_ = (float*)p_fc2T;

    static int attr_set = 0;
    if (!attr_set) {
        cudaFuncSetAttribute(attn_mma, cudaFuncAttributeMaxDynamicSharedMemorySize, ATTN_SMEM);
        cudaFuncSetAttribute(mma_gemm<1>, cudaFuncAttributeMaxDynamicSharedMemorySize, GEMM_SMEM);
        cudaFuncSetAttribute(mma_gemm<2>, cudaFuncAttributeMaxDynamicSharedMemorySize, GEMM_SMEM);
        cudaFuncSetAttribute(mma_gemm<3>, cudaFuncAttributeMaxDynamicSharedMemorySize, GEMM_SMEM);
        attr_set = 1;
    }

    // weight transposes: W[K,N] -> WT[N,K]
    transpose_k<<<dim3(3 * DIM / 32, DIM / 32), dim3(32, 8)>>>(qkv_w, qkvT_, DIM, 3 * DIM);
    transpose_k<<<dim3(DIM / 32, DIM / 32), dim3(32, 8)>>>(proj_w, projT_, DIM, DIM);
    transpose_k<<<dim3(HID / 32, DIM / 32), dim3(32, 8)>>>(fc1_w, fc1T_, DIM, HID);
    transpose_k<<<dim3(DIM / 32, HID / 32), dim3(32, 8)>>>(fc2_w, fc2T_, HID, DIM);

    // 1. LN1
    ln_kernel<<<TOK, 192>>>(x, ln1_g, ln1_b, h_);
    // 2. QKV GEMM with head-major scatter, Q pre-scaled
    mma_gemm<1><<<dim3(3 * DIM / 256, TOK / 128), 256, GEMM_SMEM>>>(
        h_, qkvT_, qkv_b, nullptr, nullptr, TOK, 3 * DIM, DIM,
        q_, k_, v_, nullptr, nullptr, nullptr);
    // 3. attention
    attn_mma<<<dim3(SEQ / 64, BH), 256, ATTN_SMEM>>>(q_, k_, v_, ao_,
                                                     attn_a, attn_b, attn_c);
    // 4. proj GEMM + residual
    mma_gemm<2><<<dim3(DIM / 256, TOK / 128), 256, GEMM_SMEM>>>(
        ao_, projT_, proj_b, x, x1_, TOK, DIM, DIM,
        nullptr, nullptr, nullptr, nullptr, nullptr, nullptr);
    // 5. LN2
    ln_kernel<<<TOK, 192>>>(x1_, ln2_g, ln2_b, h_);
    // 6. FC1 GEMM + PolyGELU
    mma_gemm<3><<<dim3(HID / 256, TOK / 128), 256, GEMM_SMEM>>>(
        h_, fc1T_, fc1_b, nullptr, u_, TOK, HID, DIM,
        nullptr, nullptr, nullptr, gelu_a, gelu_b, gelu_c);
    // 7. FC2 GEMM + residual
    mma_gemm<2><<<dim3(DIM / 256, TOK / 128), 256, GEMM_SMEM>>>(
        u_, fc2T_, fc2_b, x1_, out, TOK, DIM, HID,
        nullptr, nullptr, nullptr, nullptr, nullptr, nullptr);
}

// round 13
// speedup vs baseline: 1.0167x; 1.0167x over previous
#include <cuda_runtime.h>
#include <cuda_bf16.h>

#define TOK   8192
#define SEQ   2048
#define BATCH 4
#define DIM   768
#define NHEAD 12
#define HDIM  64
#define BH    (BATCH*NHEAD)
#define HID   3072
#define QKSCALE 0.125f
#define LN_EPS 1e-5f

// -------- scratch --------
__device__ float g_h[TOK * DIM];
__device__ float g_q[BH * SEQ * HDIM];
__device__ float g_k[BH * SEQ * HDIM];
__device__ float g_v[BH * SEQ * HDIM];
__device__ float g_attnout[TOK * DIM];
__device__ float g_x1[TOK * DIM];
__device__ float g_u[TOK * HID];
__device__ float g_qkvT[3 * DIM * DIM];
__device__ float g_projT[DIM * DIM];
__device__ float g_fc1T[HID * DIM];
__device__ float g_fc2T[DIM * HID];

// ---------- helpers ----------
__device__ __forceinline__ void mma_tf32(float& d0, float& d1, float& d2, float& d3,
                                         unsigned a0, unsigned a1, unsigned a2, unsigned a3,
                                         unsigned b0, unsigned b1)
{
    asm volatile(
        "mma.sync.aligned.m16n8k8.row.col.f32.tf32.tf32.f32 "
        "{%0,%1,%2,%3},{%4,%5,%6,%7},{%8,%9},{%0,%1,%2,%3};"
        : "+f"(d0), "+f"(d1), "+f"(d2), "+f"(d3)
        : "r"(a0), "r"(a1), "r"(a2), "r"(a3), "r"(b0), "r"(b1));
}

__device__ __forceinline__ void ldsm4(unsigned& r0, unsigned& r1, unsigned& r2, unsigned& r3,
                                      unsigned addr)
{
    asm volatile("ldmatrix.sync.aligned.m8n8.x4.shared.b16 {%0,%1,%2,%3}, [%4];"
        : "=r"(r0), "=r"(r1), "=r"(r2), "=r"(r3) : "r"(addr));
}

__device__ __forceinline__ void cp16(unsigned saddr, const void* gptr) {
    asm volatile("cp.async.cg.shared.global [%0], [%1], 16;" :: "r"(saddr), "l"(gptr));
}
#define CP_COMMIT() asm volatile("cp.async.commit_group;")
#define CP_WAIT(n)  asm volatile("cp.async.wait_group %0;" :: "n"(n))
#define BAR_PAIR(id) asm volatile("bar.sync %0, 64;" :: "r"(id) : "memory")

// ============================ LayerNorm ============================
__global__ __launch_bounds__(192) void ln_kernel(
    const float* __restrict__ x, const float* __restrict__ gamma,
    const float* __restrict__ beta, float* __restrict__ out)
{
    int row = blockIdx.x;
    int tid = threadIdx.x;
    const float* xr = x + (size_t)row * DIM;
    float4 v = *(const float4*)(xr + tid * 4);
    float s  = v.x + v.y + v.z + v.w;
    float s2 = v.x * v.x + v.y * v.y + v.z * v.z + v.w * v.w;
    #pragma unroll
    for (int o = 16; o; o >>= 1) {
        s  += __shfl_xor_sync(0xffffffffu, s,  o);
        s2 += __shfl_xor_sync(0xffffffffu, s2, o);
    }
    __shared__ float rs[6], rs2[6];
    int lane = tid & 31, wid = tid >> 5;
    if (lane == 0) { rs[wid] = s; rs2[wid] = s2; }
    __syncthreads();
    float ts = 0.f, ts2 = 0.f;
    #pragma unroll
    for (int i = 0; i < 6; i++) { ts += rs[i]; ts2 += rs2[i]; }
    float mean = ts * (1.0f / DIM);
    float var  = ts2 * (1.0f / DIM) - mean * mean;
    float inv  = rsqrtf(var + LN_EPS);
    float4 g = *(const float4*)(gamma + tid * 4);
    float4 b = *(const float4*)(beta + tid * 4);
    float4 o;
    o.x = (v.x - mean) * inv * g.x + b.x;
    o.y = (v.y - mean) * inv * g.y + b.y;
    o.z = (v.z - mean) * inv * g.z + b.z;
    o.w = (v.w - mean) * inv * g.w + b.w;
    *(float4*)(out + (size_t)row * DIM + tid * 4) = o;
}

// ============================ Weight transpose: in[K,N] -> out[N,K] ============================
__global__ __launch_bounds__(256) void transpose_k(
    const float* __restrict__ in, float* __restrict__ out, int K, int N)
{
    __shared__ float t[32][33];
    int n0 = blockIdx.x * 32, k0 = blockIdx.y * 32;
    int tx = threadIdx.x, ty = threadIdx.y;
    #pragma unroll
    for (int i = ty; i < 32; i += 8)
        t[i][tx] = in[(size_t)(k0 + i) * N + n0 + tx];
    __syncthreads();
    #pragma unroll
    for (int i = ty; i < 32; i += 8)
        out[(size_t)(n0 + i) * K + k0 + tx] = t[tx][i];
}

// ============================ TF32 GEMM 128x256, 512 thr, warp 64x32, 3-stage ============================
#define TW 36
#define A_WORDS (128 * TW)                 // 4608
#define B_WORDS (256 * TW)                 // 9216
#define STAGE_WORDS (A_WORDS + B_WORDS)    // 13824
#define GEMM_SMEM (3 * STAGE_WORDS * 4)    // 165888

__device__ __forceinline__ void load_chunk(
    unsigned sb, const float* Ag, const float* Bg, int K, int tid)
{
    #pragma unroll
    for (int i = 0; i < 2; i++) {              // A: 128 rows x 32 floats
        int idx = tid + i * 512;
        int r = idx >> 3, g = idx & 7;
        cp16(sb + (r * TW + g * 4) * 4, Ag + (size_t)r * K + g * 4);
    }
    #pragma unroll
    for (int i = 0; i < 4; i++) {              // B: 256 rows x 32 floats
        int idx = tid + i * 512;
        int r = idx >> 3, g = idx & 7;
        cp16(sb + (A_WORDS + r * TW + g * 4) * 4, Bg + (size_t)r * K + g * 4);
    }
}

template <int EPI>
__global__ __launch_bounds__(512) void mma_gemm(
    const float* __restrict__ A, const float* __restrict__ WT,
    const float* __restrict__ bias, const float* __restrict__ res,
    float* __restrict__ C, int M, int N, int K,
    float* __restrict__ qo, float* __restrict__ ko, float* __restrict__ vo,
    const float* __restrict__ c0, const float* __restrict__ c1,
    const float* __restrict__ c2)
{
    extern __shared__ unsigned smem[];

    const int tid  = threadIdx.x;
    const int lane = tid & 31;
    const int w    = tid >> 5;          // 0..15
    const int wm   = w >> 3;            // 0..1 : 64-row half
    const int wn   = w & 7;             // 0..7 : 32-col slice
    const int bx = blockIdx.x, by = blockIdx.y;

    const float* Ag = A  + (size_t)(by * 128) * K;
    const float* Bg = WT + (size_t)(bx * 256) * K;

    const unsigned sbase = (unsigned)__cvta_generic_to_shared(smem);
    const int nch = K >> 5;

    // prologue: stages 0,1
    #pragma unroll
    for (int t = 0; t < 2; t++) {
        load_chunk(sbase + t * STAGE_WORDS * 4, Ag + t * 32, Bg + t * 32, K, tid);
        CP_COMMIT();
    }

    float acc[4][4][4];
    #pragma unroll
    for (int i = 0; i < 4; i++)
        #pragma unroll
        for (int j = 0; j < 4; j++)
            #pragma unroll
            for (int r = 0; r < 4; r++) acc[i][j][r] = 0.f;

    const unsigned a_laneoff = (((lane & 7) + ((lane >> 3) & 1) * 8) * TW + (lane >> 4) * 4) * 4;
    const unsigned b_laneoff = (((lane & 7) + ((lane >> 4) & 1) * 8) * TW + ((lane >> 3) & 1) * 4) * 4;

    int stage = 0;
    for (int t = 0; t < nch; t++) {
        CP_WAIT(1);
        __syncthreads();            // single barrier per k32 tile
        if (t + 2 < nch) {
            int s2 = stage + 2; if (s2 >= 3) s2 -= 3;
            load_chunk(sbase + s2 * STAGE_WORDS * 4,
                       Ag + (t + 2) * 32, Bg + (t + 2) * 32, K, tid);
        }
        CP_COMMIT();

        const unsigned sA = sbase + stage * STAGE_WORDS * 4;
        const unsigned sB = sA + A_WORDS * 4;
        #pragma unroll
        for (int kk = 0; kk < 32; kk += 8) {
            unsigned af[4][4], bf[4][2];
            #pragma unroll
            for (int mt = 0; mt < 4; mt++) {
                unsigned addr = sA + ((wm * 64 + mt * 16) * TW + kk) * 4 + a_laneoff;
                ldsm4(af[mt][0], af[mt][1], af[mt][2], af[mt][3], addr);
            }
            #pragma unroll
            for (int p = 0; p < 2; p++) {
                unsigned addr = sB + ((wn * 32 + p * 16) * TW + kk) * 4 + b_laneoff;
                ldsm4(bf[2 * p][0], bf[2 * p][1], bf[2 * p + 1][0], bf[2 * p + 1][1], addr);
            }
            #pragma unroll
            for (int mt = 0; mt < 4; mt++)
                #pragma unroll
                for (int nt = 0; nt < 4; nt++)
                    mma_tf32(acc[mt][nt][0], acc[mt][nt][1], acc[mt][nt][2], acc[mt][nt][3],
                             af[mt][0], af[mt][1], af[mt][2], af[mt][3],
                             bf[nt][0], bf[nt][1]);
        }
        stage++; if (stage == 3) stage = 0;
    }

    float ga = 0.f, gb = 0.f, gc = 0.f;
    if (EPI == 3) { ga = *c0; gb = *c1; gc = *c2; }

    #pragma unroll
    for (int mt = 0; mt < 4; mt++) {
        #pragma unroll
        for (int nt = 0; nt < 4; nt++) {
            int r0  = by * 128 + wm * 64 + mt * 16 + (lane >> 2);
            int cc0 = bx * 256 + wn * 32 + nt * 8 + 2 * (lane & 3);
            #pragma unroll
            for (int half = 0; half < 2; half++) {
                int r = r0 + half * 8;
                float v0 = acc[mt][nt][half * 2 + 0] + bias[cc0];
                float v1 = acc[mt][nt][half * 2 + 1] + bias[cc0 + 1];
                if (EPI == 1) {
                    int which = cc0 / DIM;
                    int jj = cc0 - which * DIM;
                    int h = jj >> 6, d = jj & 63;
                    int b = r >> 11, n = r & 2047;
                    float* dst = (which == 0) ? qo : (which == 1) ? ko : vo;
                    if (which == 0) { v0 *= QKSCALE; v1 *= QKSCALE; }
                    size_t base = (((size_t)(b * NHEAD + h) * SEQ) + n) * HDIM + d;
                    dst[base] = v0; dst[base + 1] = v1;
                } else if (EPI == 2) {
                    size_t base = (size_t)r * N + cc0;
                    C[base]     = v0 + res[base];
                    C[base + 1] = v1 + res[base + 1];
                } else if (EPI == 3) {
                    size_t base = (size_t)r * N + cc0;
                    C[base]     = fmaf(v0, fmaf(ga, v0, gb), gc);
                    C[base + 1] = fmaf(v1, fmaf(ga, v1, gb), gc);
                } else {
                    size_t base = (size_t)r * N + cc0;
                    C[base] = v0; C[base + 1] = v1;
                }
            }
        }
    }
}

// ============================ Polynomial attention (round-5, proven) ============================
#define KS_W 68
#define VS_W 72
#define KS_T (64 * KS_W)
#define VS_T (64 * VS_W)
#define ATTN_SMEM ((2 * KS_T + 2 * VS_T + 64 * 68) * 4)

__global__ __launch_bounds__(256, 2) void attn_mma(
    const float* __restrict__ Q, const float* __restrict__ Kg,
    const float* __restrict__ Vg, float* __restrict__ out,
    const float* __restrict__ pa, const float* __restrict__ pb,
    const float* __restrict__ pc)
{
    extern __shared__ unsigned dsm[];
    unsigned* Ks = dsm;
    unsigned* Vs = dsm + 2 * KS_T;
    unsigned* Ss = dsm + 2 * KS_T + 2 * VS_T;
    __shared__ float rsums[64];

    const int tid  = threadIdx.x;
    const int lane = tid & 31;
    const int w    = tid >> 5;
    const int mt   = w >> 1;
    const int nh   = w & 1;
    const int bh   = blockIdx.y;
    const int n0   = blockIdx.x * 64;

    const float* Qb = Q  + (size_t)bh * SEQ * HDIM;
    const float* Kb = Kg + (size_t)bh * SEQ * HDIM;
    const float* Vb = Vg + (size_t)bh * SEQ * HDIM;

    const float aa = *pa, bb = *pb, cc = *pc;

    if (tid < 64) rsums[tid] = 0.f;

    const int grow = tid >> 4;
    const int gc4  = tid & 15;

    const unsigned sKs = (unsigned)__cvta_generic_to_shared(Ks);
    const unsigned sVs = (unsigned)__cvta_generic_to_shared(Vs);
    const unsigned sSs = (unsigned)__cvta_generic_to_shared(Ss);

    #pragma unroll
    for (int it = 0; it < 4; it++) {
        int r = it * 16 + grow;
        cp16(sSs + (r * 68 + gc4 * 4) * 4, Qb + (size_t)(n0 + r) * HDIM + gc4 * 4);
    }
    CP_COMMIT();
    #pragma unroll
    for (int t = 0; t < 2; t++) {
        #pragma unroll
        for (int it = 0; it < 4; it++) {
            int r = it * 16 + grow;
            cp16(sKs + (t * KS_T + r * KS_W + gc4 * 4) * 4,
                 Kb + (size_t)(t * 64 + r) * HDIM + gc4 * 4);
            cp16(sVs + (t * VS_T + r * VS_W + gc4 * 4) * 4,
                 Vb + (size_t)(t * 64 + r) * HDIM + gc4 * 4);
        }
        CP_COMMIT();
    }
    CP_WAIT(2);
    __syncthreads();

    const unsigned a_laneoff = (((lane & 7) + ((lane >> 3) & 1) * 8) * 68 + (lane >> 4) * 4) * 4;
    const unsigned b_laneoff = (((lane & 7) + ((lane >> 4) & 1) * 8) * KS_W + ((lane >> 3) & 1) * 4) * 4;

    unsigned qf[8][4];
    #pragma unroll
    for (int kk = 0; kk < 8; kk++) {
        unsigned addr = sSs + (mt * 16 * 68 + kk * 8) * 4 + a_laneoff;
        ldsm4(qf[kk][0], qf[kk][1], qf[kk][2], qf[kk][3], addr);
    }

    float oacc[4][4];
    #pragma unroll
    for (int ntt = 0; ntt < 4; ntt++)
        #pragma unroll
        for (int r = 0; r < 4; r++) oacc[ntt][r] = 0.f;
    float rs0 = 0.f, rs1 = 0.f;

    for (int m = 0; m < 32; m++) {
        const int buf = m & 1;
        CP_WAIT(1);
        __syncthreads();

        float sacc[4][4];
        #pragma unroll
        for (int ntt = 0; ntt < 4; ntt++)
            #pragma unroll
            for (int r = 0; r < 4; r++) sacc[ntt][r] = 0.f;

        unsigned kbase = sKs + buf * KS_T * 4;
        #pragma unroll
        for (int kk = 0; kk < 8; kk++) {
            unsigned bf[4][2];
            #pragma unroll
            for (int p = 0; p < 2; p++) {
                unsigned addr = kbase + ((nh * 32 + p * 16) * KS_W + kk * 8) * 4 + b_laneoff;
                ldsm4(bf[2 * p][0], bf[2 * p][1], bf[2 * p + 1][0], bf[2 * p + 1][1], addr);
            }
            #pragma unroll
            for (int ntt = 0; ntt < 4; ntt++)
                mma_tf32(sacc[ntt][0], sacc[ntt][1], sacc[ntt][2], sacc[ntt][3],
                         qf[kk][0], qf[kk][1], qf[kk][2], qf[kk][3],
                         bf[ntt][0], bf[ntt][1]);
        }

        #pragma unroll
        for (int ntt = 0; ntt < 4; ntt++) {
            #pragma unroll
            for (int r = 0; r < 4; r++) {
                float t = sacc[ntt][r];
                t = fmaf(t, fmaf(aa, t, bb), cc);
                t = fmaxf(t, 1e-6f);
                sacc[ntt][r] = t;
                if (r < 2) rs0 += t; else rs1 += t;
            }
        }

        #pragma unroll
        for (int ntt = 0; ntt < 4; ntt++) {
            int row = mt * 16 + (lane >> 2);
            int col = nh * 32 + ntt * 8 + 2 * (lane & 3);
            uint2 u0 = make_uint2(__float_as_uint(sacc[ntt][0]), __float_as_uint(sacc[ntt][1]));
            uint2 u1 = make_uint2(__float_as_uint(sacc[ntt][2]), __float_as_uint(sacc[ntt][3]));
            *(uint2*)&Ss[row * 68 + col]       = u0;
            *(uint2*)&Ss[(row + 8) * 68 + col] = u1;
        }
        BAR_PAIR(1 + mt);

        const unsigned* Vbuf = Vs + buf * VS_T;
        #pragma unroll
        for (int kk = 0; kk < 8; kk++) {
            unsigned af[4];
            unsigned addr = sSs + (mt * 16 * 68 + kk * 8) * 4 + a_laneoff;
            ldsm4(af[0], af[1], af[2], af[3], addr);
            unsigned bfv[4][2];
            #pragma unroll
            for (int ntt = 0; ntt < 4; ntt++) {
                int dcol = nh * 32 + ntt * 8 + (lane >> 2);
                bfv[ntt][0] = Vbuf[(kk * 8 + (lane & 3)) * VS_W + dcol];
                bfv[ntt][1] = Vbuf[(kk * 8 + (lane & 3) + 4) * VS_W + dcol];
            }
            #pragma unroll
            for (int ntt = 0; ntt < 4; ntt++)
                mma_tf32(oacc[ntt][0], oacc[ntt][1], oacc[ntt][2], oacc[ntt][3],
                         af[0], af[1], af[2], af[3],
                         bfv[ntt][0], bfv[ntt][1]);
        }
        __syncthreads();

        if (m + 2 < 32) {
            int tt = m + 2;
            #pragma unroll
            for (int it = 0; it < 4; it++) {
                int r = it * 16 + grow;
                cp16(sKs + (buf * KS_T + r * KS_W + gc4 * 4) * 4,
                     Kb + (size_t)(tt * 64 + r) * HDIM + gc4 * 4);
                cp16(sVs + (buf * VS_T + r * VS_W + gc4 * 4) * 4,
                     Vb + (size_t)(tt * 64 + r) * HDIM + gc4 * 4);
            }
        }
        CP_COMMIT();
    }

    rs0 += __shfl_xor_sync(0xffffffffu, rs0, 1);
    rs0 += __shfl_xor_sync(0xffffffffu, rs0, 2);
    rs1 += __shfl_xor_sync(0xffffffffu, rs1, 1);
    rs1 += __shfl_xor_sync(0xffffffffu, rs1, 2);
    if ((lane & 3) == 0) {
        atomicAdd(&rsums[mt * 16 + (lane >> 2)], rs0);
        atomicAdd(&rsums[mt * 16 + (lane >> 2) + 8], rs1);
    }
    __syncthreads();

    int b = bh / NHEAD, h = bh % NHEAD;
    int row0 = mt * 16 + (lane >> 2);
    float inv0 = 1.0f / (rsums[row0] + 1e-8f);
    float inv1 = 1.0f / (rsums[row0 + 8] + 1e-8f);
    #pragma unroll
    for (int ntt = 0; ntt < 4; ntt++) {
        int d = nh * 32 + ntt * 8 + 2 * (lane & 3);
        size_t base0 = ((size_t)(b * SEQ + n0 + row0)) * DIM + h * HDIM + d;
        size_t base1 = ((size_t)(b * SEQ + n0 + row0 + 8)) * DIM + h * HDIM + d;
        out[base0]     = oacc[ntt][0] * inv0;
        out[base0 + 1] = oacc[ntt][1] * inv0;
        out[base1]     = oacc[ntt][2] * inv1;
        out[base1 + 1] = oacc[ntt][3] * inv1;
    }
}

// ============================ launch ============================
extern "C" void kernel_launch(void* const* d_in, const int* in_sizes, int n_in,
                              void* d_out, int out_size)
{
    const float* x      = (const float*)d_in[0];
    const float* ln1_g  = (const float*)d_in[1];
    const float* ln1_b  = (const float*)d_in[2];
    const float* ln2_g  = (const float*)d_in[3];
    const float* ln2_b  = (const float*)d_in[4];
    const float* qkv_w  = (const float*)d_in[5];
    const float* qkv_b  = (const float*)d_in[6];
    const float* proj_w = (const float*)d_in[7];
    const float* proj_b = (const float*)d_in[8];
    const float* fc1_w  = (const float*)d_in[9];
    const float* fc1_b  = (const float*)d_in[10];
    const float* fc2_w  = (const float*)d_in[11];
    const float* fc2_b  = (const float*)d_in[12];
    const float* attn_a = (const float*)d_in[13];
    const float* attn_b = (const float*)d_in[14];
    const float* attn_c = (const float*)d_in[15];
    const float* gelu_a = (const float*)d_in[16];
    const float* gelu_b = (const float*)d_in[17];
    const float* gelu_c = (const float*)d_in[18];
    float* out = (float*)d_out;

    void *p_h, *p_q, *p_k, *p_v, *p_ao, *p_x1, *p_u;
    void *p_qkvT, *p_projT, *p_fc1T, *p_fc2T;
    cudaGetSymbolAddress(&p_h,  g_h);
    cudaGetSymbolAddress(&p_q,  g_q);
    cudaGetSymbolAddress(&p_k,  g_k);
    cudaGetSymbolAddress(&p_v,  g_v);
    cudaGetSymbolAddress(&p_ao, g_attnout);
    cudaGetSymbolAddress(&p_x1, g_x1);
    cudaGetSymbolAddress(&p_u,  g_u);
    cudaGetSymbolAddress(&p_qkvT, g_qkvT);
    cudaGetSymbolAddress(&p_projT, g_projT);
    cudaGetSymbolAddress(&p_fc1T, g_fc1T);
    cudaGetSymbolAddress(&p_fc2T, g_fc2T);
    float* h_  = (float*)p_h;
    float* q_  = (float*)p_q;
    float* k_  = (float*)p_k;
    float* v_  = (float*)p_v;
    float* ao_ = (float*)p_ao;
    float* x1_ = (float*)p_x1;
    float* u_  = (float*)p_u;
    float* qkvT_ = (float*)p_qkvT;
    float* projT_ = (float*)p_projT;
    float* fc1T_ = (float*)p_fc1T;
    float* fc2T_ = (float*)p_fc2T;

    static int attr_set = 0;
    if (!attr_set) {
        cudaFuncSetAttribute(attn_mma, cudaFuncAttributeMaxDynamicSharedMemorySize, ATTN_SMEM);
        cudaFuncSetAttribute(mma_gemm<1>, cudaFuncAttributeMaxDynamicSharedMemorySize, GEMM_SMEM);
        cudaFuncSetAttribute(mma_gemm<2>, cudaFuncAttributeMaxDynamicSharedMemorySize, GEMM_SMEM);
        cudaFuncSetAttribute(mma_gemm<3>, cudaFuncAttributeMaxDynamicSharedMemorySize, GEMM_SMEM);
        attr_set = 1;
    }

    // weight transposes: W[K,N] -> WT[N,K]
    transpose_k<<<dim3(3 * DIM / 32, DIM / 32), dim3(32, 8)>>>(qkv_w, qkvT_, DIM, 3 * DIM);
    transpose_k<<<dim3(DIM / 32, DIM / 32), dim3(32, 8)>>>(proj_w, projT_, DIM, DIM);
    transpose_k<<<dim3(HID / 32, DIM / 32), dim3(32, 8)>>>(fc1_w, fc1T_, DIM, HID);
    transpose_k<<<dim3(DIM / 32, HID / 32), dim3(32, 8)>>>(fc2_w, fc2T_, HID, DIM);

    // 1. LN1
    ln_kernel<<<TOK, 192>>>(x, ln1_g, ln1_b, h_);
    // 2. QKV GEMM with head-major scatter, Q pre-scaled
    mma_gemm<1><<<dim3(3 * DIM / 256, TOK / 128), 512, GEMM_SMEM>>>(
        h_, qkvT_, qkv_b, nullptr, nullptr, TOK, 3 * DIM, DIM,
        q_, k_, v_, nullptr, nullptr, nullptr);
    // 3. attention
    attn_mma<<<dim3(SEQ / 64, BH), 256, ATTN_SMEM>>>(q_, k_, v_, ao_,
                                                     attn_a, attn_b, attn_c);
    // 4. proj GEMM + residual
    mma_gemm<2><<<dim3(DIM / 256, TOK / 128), 512, GEMM_SMEM>>>(
        ao_, projT_, proj_b, x, x1_, TOK, DIM, DIM,
        nullptr, nullptr, nullptr, nullptr, nullptr, nullptr);
    // 5. LN2
    ln_kernel<<<TOK, 192>>>(x1_, ln2_g, ln2_b, h_);
    // 6. FC1 GEMM + PolyGELU
    mma_gemm<3><<<dim3(HID / 256, TOK / 128), 512, GEMM_SMEM>>>(
        h_, fc1T_, fc1_b, nullptr, u_, TOK, HID, DIM,
        nullptr, nullptr, nullptr, gelu_a, gelu_b, gelu_c);
    // 7. FC2 GEMM + residual
    mma_gemm<2><<<dim3(DIM / 256, TOK / 128), 512, GEMM_SMEM>>>(
        u_, fc2T_, fc2_b, x1_, out, TOK, DIM, HID,
        nullptr, nullptr, nullptr, nullptr, nullptr, nullptr);
}

// round 14
// speedup vs baseline: 1.1556x; 1.1366x over previous
#include <cuda_runtime.h>
#include <cuda_bf16.h>

#define TOK   8192
#define SEQ   2048
#define BATCH 4
#define DIM   768
#define NHEAD 12
#define HDIM  64
#define BH    (BATCH*NHEAD)
#define HID   3072
#define QKSCALE 0.125f
#define LN_EPS 1e-5f

__device__ float g_h[TOK * DIM];
__device__ float g_q[BH * SEQ * HDIM];
__device__ float g_k[BH * SEQ * HDIM];
__device__ float g_v[BH * SEQ * HDIM];
__device__ float g_attnout[TOK * DIM];
__device__ float g_x1[TOK * DIM];
__device__ float g_u[TOK * HID];

__device__ __forceinline__ void mma_tf32(float& d0, float& d1, float& d2, float& d3,
                                         unsigned a0, unsigned a1, unsigned a2, unsigned a3,
                                         unsigned b0, unsigned b1)
{
    asm volatile(
        "mma.sync.aligned.m16n8k8.row.col.f32.tf32.tf32.f32 "
        "{%0,%1,%2,%3},{%4,%5,%6,%7},{%8,%9},{%0,%1,%2,%3};"
        : "+f"(d0), "+f"(d1), "+f"(d2), "+f"(d3)
        : "r"(a0), "r"(a1), "r"(a2), "r"(a3), "r"(b0), "r"(b1));
}

__device__ __forceinline__ void ldsm4(unsigned& r0, unsigned& r1, unsigned& r2, unsigned& r3,
                                      unsigned addr)
{
    asm volatile("ldmatrix.sync.aligned.m8n8.x4.shared.b16 {%0,%1,%2,%3}, [%4];"
        : "=r"(r0), "=r"(r1), "=r"(r2), "=r"(r3) : "r"(addr));
}

__device__ __forceinline__ void cp16(unsigned saddr, const void* gptr) {
    asm volatile("cp.async.cg.shared.global [%0], [%1], 16;" :: "r"(saddr), "l"(gptr));
}
#define CP_COMMIT() asm volatile("cp.async.commit_group;")
#define CP_WAIT(n)  asm volatile("cp.async.wait_group %0;" :: "n"(n))
#define BAR_PAIR(id) asm volatile("bar.sync %0, 64;" :: "r"(id) : "memory")

// ============================ LayerNorm ============================
__global__ __launch_bounds__(192) void ln_kernel(
    const float* __restrict__ x, const float* __restrict__ gamma,
    const float* __restrict__ beta, float* __restrict__ out)
{
    int row = blockIdx.x;
    int tid = threadIdx.x;
    const float* xr = x + (size_t)row * DIM;
    float4 v = *(const float4*)(xr + tid * 4);
    float s  = v.x + v.y + v.z + v.w;
    float s2 = v.x * v.x + v.y * v.y + v.z * v.z + v.w * v.w;
    #pragma unroll
    for (int o = 16; o; o >>= 1) {
        s  += __shfl_xor_sync(0xffffffffu, s,  o);
        s2 += __shfl_xor_sync(0xffffffffu, s2, o);
    }
    __shared__ float rs[6], rs2[6];
    int lane = tid & 31, wid = tid >> 5;
    if (lane == 0) { rs[wid] = s; rs2[wid] = s2; }
    __syncthreads();
    float ts = 0.f, ts2 = 0.f;
    #pragma unroll
    for (int i = 0; i < 6; i++) { ts += rs[i]; ts2 += rs2[i]; }
    float mean = ts * (1.0f / DIM);
    float var  = ts2 * (1.0f / DIM) - mean * mean;
    float inv  = rsqrtf(var + LN_EPS);
    float4 g = *(const float4*)(gamma + tid * 4);
    float4 b = *(const float4*)(beta + tid * 4);
    float4 o;
    o.x = (v.x - mean) * inv * g.x + b.x;
    o.y = (v.y - mean) * inv * g.y + b.y;
    o.z = (v.z - mean) * inv * g.z + b.z;
    o.w = (v.w - mean) * inv * g.w + b.w;
    *(float4*)(out + (size_t)row * DIM + tid * 4) = o;
}

// ============================ TF32 GEMM (round-5 proven): 128x128, k32, 3-stage ============================
#define AS_W 36
#define BS_W 136
#define AS_STAGE (128 * AS_W)
#define BS_STAGE (32 * BS_W)
#define STAGE_W  (AS_STAGE + BS_STAGE)
#define GEMM_SMEM (3 * STAGE_W * 4)

template <int EPI>
__global__ __launch_bounds__(256, 2) void mma_gemm(
    const float* __restrict__ A, const float* __restrict__ W,
    const float* __restrict__ bias, const float* __restrict__ res,
    float* __restrict__ C, int M, int N, int K,
    float* __restrict__ qo, float* __restrict__ ko, float* __restrict__ vo,
    const float* __restrict__ c0, const float* __restrict__ c1,
    const float* __restrict__ c2)
{
    extern __shared__ unsigned smem[];

    const int tid  = threadIdx.x;
    const int lane = tid & 31;
    const int w    = tid >> 5;
    const int wm   = w >> 2;
    const int wn   = w & 3;
    const int bx = blockIdx.x, by = blockIdx.y;

    const int arow = tid >> 3, ac4 = tid & 7;
    const int brow = tid >> 5, bc4 = tid & 31;

    const float* Ag = A + (size_t)(by * 128 + arow) * K + ac4 * 4;
    const float* Bg = W + (size_t)brow * N + bx * 128 + bc4 * 4;

    const unsigned sbase = (unsigned)__cvta_generic_to_shared(smem);
    const int nt = K >> 5;

    #pragma unroll
    for (int t = 0; t < 2; t++) {
        unsigned sb = sbase + t * STAGE_W * 4;
        #pragma unroll
        for (int p = 0; p < 4; p++) {
            cp16(sb + ((arow + p * 32) * AS_W + ac4 * 4) * 4,
                 Ag + (size_t)p * 32 * K + t * 32);
            cp16(sb + (AS_STAGE + (brow + p * 8) * BS_W + bc4 * 4) * 4,
                 Bg + (size_t)(t * 32 + p * 8) * N);
        }
        CP_COMMIT();
    }

    float acc[4][4][4];
    #pragma unroll
    for (int i = 0; i < 4; i++)
        #pragma unroll
        for (int j = 0; j < 4; j++)
            #pragma unroll
            for (int r = 0; r < 4; r++) acc[i][j][r] = 0.f;

    const unsigned a_laneoff = (((lane & 7) + ((lane >> 3) & 1) * 8) * AS_W + (lane >> 4) * 4) * 4;

    int stage = 0;
    for (int t = 0; t < nt; t++) {
        CP_WAIT(1);
        __syncthreads();
        if (t + 2 < nt) {
            int s2 = stage + 2; if (s2 >= 3) s2 -= 3;
            unsigned sb = sbase + s2 * STAGE_W * 4;
            int tt = t + 2;
            #pragma unroll
            for (int p = 0; p < 4; p++) {
                cp16(sb + ((arow + p * 32) * AS_W + ac4 * 4) * 4,
                     Ag + (size_t)p * 32 * K + tt * 32);
                cp16(sb + (AS_STAGE + (brow + p * 8) * BS_W + bc4 * 4) * 4,
                     Bg + (size_t)(tt * 32 + p * 8) * N);
            }
        }
        CP_COMMIT();

        unsigned sA = sbase + stage * STAGE_W * 4;
        const unsigned* BsS = smem + stage * STAGE_W + AS_STAGE;
        #pragma unroll
        for (int kk = 0; kk < 32; kk += 8) {
            unsigned af[4][4], bf[4][2];
            #pragma unroll
            for (int mt = 0; mt < 4; mt++) {
                unsigned addr = sA + ((wm * 64 + mt * 16) * AS_W + kk) * 4 + a_laneoff;
                ldsm4(af[mt][0], af[mt][1], af[mt][2], af[mt][3], addr);
            }
            #pragma unroll
            for (int ntt = 0; ntt < 4; ntt++) {
                int col = wn * 32 + ntt * 8 + (lane >> 2);
                bf[ntt][0] = BsS[(kk + (lane & 3)) * BS_W + col];
                bf[ntt][1] = BsS[(kk + (lane & 3) + 4) * BS_W + col];
            }
            #pragma unroll
            for (int mt = 0; mt < 4; mt++)
                #pragma unroll
                for (int ntt = 0; ntt < 4; ntt++)
                    mma_tf32(acc[mt][ntt][0], acc[mt][ntt][1], acc[mt][ntt][2], acc[mt][ntt][3],
                             af[mt][0], af[mt][1], af[mt][2], af[mt][3],
                             bf[ntt][0], bf[ntt][1]);
        }
        stage++; if (stage == 3) stage = 0;
    }

    float ga = 0.f, gb = 0.f, gc = 0.f;
    if (EPI == 3) { ga = *c0; gb = *c1; gc = *c2; }

    #pragma unroll
    for (int mt = 0; mt < 4; mt++) {
        #pragma unroll
        for (int ntt = 0; ntt < 4; ntt++) {
            int r0  = by * 128 + wm * 64 + mt * 16 + (lane >> 2);
            int cc0 = bx * 128 + wn * 32 + ntt * 8 + 2 * (lane & 3);
            #pragma unroll
            for (int half = 0; half < 2; half++) {
                int r = r0 + half * 8;
                float v0 = acc[mt][ntt][half * 2 + 0] + bias[cc0];
                float v1 = acc[mt][ntt][half * 2 + 1] + bias[cc0 + 1];
                if (EPI == 1) {
                    int which = cc0 / DIM;
                    int jj = cc0 - which * DIM;
                    int h = jj >> 6, d = jj & 63;
                    int b = r >> 11, n = r & 2047;
                    float* dst = (which == 0) ? qo : (which == 1) ? ko : vo;
                    if (which == 0) { v0 *= QKSCALE; v1 *= QKSCALE; }
                    size_t base = (((size_t)(b * NHEAD + h) * SEQ) + n) * HDIM + d;
                    dst[base] = v0; dst[base + 1] = v1;
                } else if (EPI == 2) {
                    size_t base = (size_t)r * N + cc0;
                    C[base]     = v0 + res[base];
                    C[base + 1] = v1 + res[base + 1];
                } else if (EPI == 3) {
                    size_t base = (size_t)r * N + cc0;
                    C[base]     = fmaf(v0, fmaf(ga, v0, gb), gc);
                    C[base + 1] = fmaf(v1, fmaf(ga, v1, gb), gc);
                } else {
                    size_t base = (size_t)r * N + cc0;
                    C[base] = v0; C[base + 1] = v1;
                }
            }
        }
    }
}

// ============================ Polynomial attention: Q-tile 128, 512 threads ============================
// smem: Ks 2x[64][68], Vs 2x[64][72], Ss [128][68]  = 104 KB
#define KS_W 68
#define VS_W 72
#define KS_T (64 * KS_W)
#define VS_T (64 * VS_W)
#define SS_T (128 * 68)
#define ATTN_SMEM ((2 * KS_T + 2 * VS_T + SS_T) * 4)

__global__ __launch_bounds__(512) void attn_mma(
    const float* __restrict__ Q, const float* __restrict__ Kg,
    const float* __restrict__ Vg, float* __restrict__ out,
    const float* __restrict__ pa, const float* __restrict__ pb,
    const float* __restrict__ pc)
{
    extern __shared__ unsigned dsm[];
    unsigned* Ks = dsm;
    unsigned* Vs = dsm + 2 * KS_T;
    unsigned* Ss = dsm + 2 * KS_T + 2 * VS_T;
    __shared__ float rsums[128];

    const int tid  = threadIdx.x;
    const int lane = tid & 31;
    const int w    = tid >> 5;          // 0..15
    const int mt   = w >> 1;            // 0..7 : 16-row group
    const int nh   = w & 1;             // 0..1 : 32-col half
    const int bh   = blockIdx.y;
    const int n0   = blockIdx.x * 128;

    const float* Qb = Q  + (size_t)bh * SEQ * HDIM;
    const float* Kb = Kg + (size_t)bh * SEQ * HDIM;
    const float* Vb = Vg + (size_t)bh * SEQ * HDIM;

    const float aa = *pa, bb = *pb, cc = *pc;

    if (tid < 128) rsums[tid] = 0.f;

    const int grow = tid >> 4;          // 0..31
    const int gc4  = tid & 15;

    const unsigned sKs = (unsigned)__cvta_generic_to_shared(Ks);
    const unsigned sVs = (unsigned)__cvta_generic_to_shared(Vs);
    const unsigned sSs = (unsigned)__cvta_generic_to_shared(Ss);

    // stage Q (128 rows) into Ss
    #pragma unroll
    for (int it = 0; it < 4; it++) {
        int r = it * 32 + grow;
        cp16(sSs + (r * 68 + gc4 * 4) * 4, Qb + (size_t)(n0 + r) * HDIM + gc4 * 4);
    }
    CP_COMMIT();
    // prologue K/V tiles 0,1 (64 keys each)
    #pragma unroll
    for (int t = 0; t < 2; t++) {
        #pragma unroll
        for (int it = 0; it < 2; it++) {
            int r = it * 32 + grow;
            cp16(sKs + (t * KS_T + r * KS_W + gc4 * 4) * 4,
                 Kb + (size_t)(t * 64 + r) * HDIM + gc4 * 4);
            cp16(sVs + (t * VS_T + r * VS_W + gc4 * 4) * 4,
                 Vb + (size_t)(t * 64 + r) * HDIM + gc4 * 4);
        }
        CP_COMMIT();
    }
    CP_WAIT(2);
    __syncthreads();

    const unsigned a_laneoff = (((lane & 7) + ((lane >> 3) & 1) * 8) * 68 + (lane >> 4) * 4) * 4;
    const unsigned b_laneoff = (((lane & 7) + ((lane >> 4) & 1) * 8) * KS_W + ((lane >> 3) & 1) * 4) * 4;

    unsigned qf[8][4];
    #pragma unroll
    for (int kk = 0; kk < 8; kk++) {
        unsigned addr = sSs + (mt * 16 * 68 + kk * 8) * 4 + a_laneoff;
        ldsm4(qf[kk][0], qf[kk][1], qf[kk][2], qf[kk][3], addr);
    }

    float oacc[4][4];
    #pragma unroll
    for (int ntt = 0; ntt < 4; ntt++)
        #pragma unroll
        for (int r = 0; r < 4; r++) oacc[ntt][r] = 0.f;
    float rs0 = 0.f, rs1 = 0.f;

    for (int m = 0; m < 32; m++) {
        const int buf = m & 1;
        CP_WAIT(1);
        __syncthreads();

        float sacc[4][4];
        #pragma unroll
        for (int ntt = 0; ntt < 4; ntt++)
            #pragma unroll
            for (int r = 0; r < 4; r++) sacc[ntt][r] = 0.f;

        unsigned kbase = sKs + buf * KS_T * 4;
        #pragma unroll
        for (int kk = 0; kk < 8; kk++) {
            unsigned bf[4][2];
            #pragma unroll
            for (int p = 0; p < 2; p++) {
                unsigned addr = kbase + ((nh * 32 + p * 16) * KS_W + kk * 8) * 4 + b_laneoff;
                ldsm4(bf[2 * p][0], bf[2 * p][1], bf[2 * p + 1][0], bf[2 * p + 1][1], addr);
            }
            #pragma unroll
            for (int ntt = 0; ntt < 4; ntt++)
                mma_tf32(sacc[ntt][0], sacc[ntt][1], sacc[ntt][2], sacc[ntt][3],
                         qf[kk][0], qf[kk][1], qf[kk][2], qf[kk][3],
                         bf[ntt][0], bf[ntt][1]);
        }

        #pragma unroll
        for (int ntt = 0; ntt < 4; ntt++) {
            #pragma unroll
            for (int r = 0; r < 4; r++) {
                float t = sacc[ntt][r];
                t = fmaf(t, fmaf(aa, t, bb), cc);
                t = fmaxf(t, 1e-6f);
                sacc[ntt][r] = t;
                if (r < 2) rs0 += t; else rs1 += t;
            }
        }

        #pragma unroll
        for (int ntt = 0; ntt < 4; ntt++) {
            int row = mt * 16 + (lane >> 2);
            int col = nh * 32 + ntt * 8 + 2 * (lane & 3);
            uint2 u0 = make_uint2(__float_as_uint(sacc[ntt][0]), __float_as_uint(sacc[ntt][1]));
            uint2 u1 = make_uint2(__float_as_uint(sacc[ntt][2]), __float_as_uint(sacc[ntt][3]));
            *(uint2*)&Ss[row * 68 + col]       = u0;
            *(uint2*)&Ss[(row + 8) * 68 + col] = u1;
        }
        BAR_PAIR(1 + mt);     // ids 1..8, 64 threads (the two warps sharing rows mt*16..+15)

        const unsigned* Vbuf = Vs + buf * VS_T;
        #pragma unroll
        for (int kk = 0; kk < 8; kk++) {
            unsigned af[4];
            unsigned addr = sSs + (mt * 16 * 68 + kk * 8) * 4 + a_laneoff;
            ldsm4(af[0], af[1], af[2], af[3], addr);
            unsigned bfv[4][2];
            #pragma unroll
            for (int ntt = 0; ntt < 4; ntt++) {
                int dcol = nh * 32 + ntt * 8 + (lane >> 2);
                bfv[ntt][0] = Vbuf[(kk * 8 + (lane & 3)) * VS_W + dcol];
                bfv[ntt][1] = Vbuf[(kk * 8 + (lane & 3) + 4) * VS_W + dcol];
            }
            #pragma unroll
            for (int ntt = 0; ntt < 4; ntt++)
                mma_tf32(oacc[ntt][0], oacc[ntt][1], oacc[ntt][2], oacc[ntt][3],
                         af[0], af[1], af[2], af[3],
                         bfv[ntt][0], bfv[ntt][1]);
        }
        __syncthreads();

        if (m + 2 < 32) {
            int tt = m + 2;
            #pragma unroll
            for (int it = 0; it < 2; it++) {
                int r = it * 32 + grow;
                cp16(sKs + (buf * KS_T + r * KS_W + gc4 * 4) * 4,
                     Kb + (size_t)(tt * 64 + r) * HDIM + gc4 * 4);
                cp16(sVs + (buf * VS_T + r * VS_W + gc4 * 4) * 4,
                     Vb + (size_t)(tt * 64 + r) * HDIM + gc4 * 4);
            }
        }
        CP_COMMIT();
    }

    rs0 += __shfl_xor_sync(0xffffffffu, rs0, 1);
    rs0 += __shfl_xor_sync(0xffffffffu, rs0, 2);
    rs1 += __shfl_xor_sync(0xffffffffu, rs1, 1);
    rs1 += __shfl_xor_sync(0xffffffffu, rs1, 2);
    if ((lane & 3) == 0) {
        atomicAdd(&rsums[mt * 16 + (lane >> 2)], rs0);
        atomicAdd(&rsums[mt * 16 + (lane >> 2) + 8], rs1);
    }
    __syncthreads();

    int b = bh / NHEAD, h = bh % NHEAD;
    int row0 = mt * 16 + (lane >> 2);
    float inv0 = 1.0f / (rsums[row0] + 1e-8f);
    float inv1 = 1.0f / (rsums[row0 + 8] + 1e-8f);
    #pragma unroll
    for (int ntt = 0; ntt < 4; ntt++) {
        int d = nh * 32 + ntt * 8 + 2 * (lane & 3);
        size_t base0 = ((size_t)(b * SEQ + n0 + row0)) * DIM + h * HDIM + d;
        size_t base1 = ((size_t)(b * SEQ + n0 + row0 + 8)) * DIM + h * HDIM + d;
        out[base0]     = oacc[ntt][0] * inv0;
        out[base0 + 1] = oacc[ntt][1] * inv0;
        out[base1]     = oacc[ntt][2] * inv1;
        out[base1 + 1] = oacc[ntt][3] * inv1;
    }
}

// ============================ launch ============================
extern "C" void kernel_launch(void* const* d_in, const int* in_sizes, int n_in,
                              void* d_out, int out_size)
{
    const float* x      = (const float*)d_in[0];
    const float* ln1_g  = (const float*)d_in[1];
    const float* ln1_b  = (const float*)d_in[2];
    const float* ln2_g  = (const float*)d_in[3];
    const float* ln2_b  = (const float*)d_in[4];
    const float* qkv_w  = (const float*)d_in[5];
    const float* qkv_b  = (const float*)d_in[6];
    const float* proj_w = (const float*)d_in[7];
    const float* proj_b = (const float*)d_in[8];
    const float* fc1_w  = (const float*)d_in[9];
    const float* fc1_b  = (const float*)d_in[10];
    const float* fc2_w  = (const float*)d_in[11];
    const float* fc2_b  = (const float*)d_in[12];
    const float* attn_a = (const float*)d_in[13];
    const float* attn_b = (const float*)d_in[14];
    const float* attn_c = (const float*)d_in[15];
    const float* gelu_a = (const float*)d_in[16];
    const float* gelu_b = (const float*)d_in[17];
    const float* gelu_c = (const float*)d_in[18];
    float* out = (float*)d_out;

    void *p_h, *p_q, *p_k, *p_v, *p_ao, *p_x1, *p_u;
    cudaGetSymbolAddress(&p_h,  g_h);
    cudaGetSymbolAddress(&p_q,  g_q);
    cudaGetSymbolAddress(&p_k,  g_k);
    cudaGetSymbolAddress(&p_v,  g_v);
    cudaGetSymbolAddress(&p_ao, g_attnout);
    cudaGetSymbolAddress(&p_x1, g_x1);
    cudaGetSymbolAddress(&p_u,  g_u);
    float* h_  = (float*)p_h;
    float* q_  = (float*)p_q;
    float* k_  = (float*)p_k;
    float* v_  = (float*)p_v;
    float* ao_ = (float*)p_ao;
    float* x1_ = (float*)p_x1;
    float* u_  = (float*)p_u;

    static int attr_set = 0;
    if (!attr_set) {
        cudaFuncSetAttribute(attn_mma, cudaFuncAttributeMaxDynamicSharedMemorySize, ATTN_SMEM);
        cudaFuncSetAttribute(mma_gemm<1>, cudaFuncAttributeMaxDynamicSharedMemorySize, GEMM_SMEM);
        cudaFuncSetAttribute(mma_gemm<2>, cudaFuncAttributeMaxDynamicSharedMemorySize, GEMM_SMEM);
        cudaFuncSetAttribute(mma_gemm<3>, cudaFuncAttributeMaxDynamicSharedMemorySize, GEMM_SMEM);
        attr_set = 1;
    }

    ln_kernel<<<TOK, 192>>>(x, ln1_g, ln1_b, h_);
    mma_gemm<1><<<dim3(3 * DIM / 128, TOK / 128), 256, GEMM_SMEM>>>(
        h_, qkv_w, qkv_b, nullptr, nullptr, TOK, 3 * DIM, DIM,
        q_, k_, v_, nullptr, nullptr, nullptr);
    attn_mma<<<dim3(SEQ / 128, BH), 512, ATTN_SMEM>>>(q_, k_, v_, ao_,
                                                      attn_a, attn_b, attn_c);
    mma_gemm<2><<<dim3(DIM / 128, TOK / 128), 256, GEMM_SMEM>>>(
        ao_, proj_w, proj_b, x, x1_, TOK, DIM, DIM,
        nullptr, nullptr, nullptr, nullptr, nullptr, nullptr);
    ln_kernel<<<TOK, 192>>>(x1_, ln2_g, ln2_b, h_);
    mma_gemm<3><<<dim3(HID / 128, TOK / 128), 256, GEMM_SMEM>>>(
        h_, fc1_w, fc1_b, nullptr, u_, TOK, HID, DIM,
        nullptr, nullptr, nullptr, gelu_a, gelu_b, gelu_c);
    mma_gemm<2><<<dim3(DIM / 128, TOK / 128), 256, GEMM_SMEM>>>(
        u_, fc2_w, fc2_b, x1_, out, TOK, DIM, HID,
        nullptr, nullptr, nullptr, nullptr, nullptr, nullptr);
}

// round 16
// speedup vs baseline: 1.1769x; 1.0185x over previous
#include <cuda_runtime.h>
#include <cuda_bf16.h>

#define TOK   8192
#define SEQ   2048
#define BATCH 4
#define DIM   768
#define NHEAD 12
#define HDIM  64
#define BH    (BATCH*NHEAD)
#define HID   3072
#define QKSCALE 0.125f
#define LN_EPS 1e-5f

__device__ float g_h[TOK * DIM];
__device__ float g_q[BH * SEQ * HDIM];
__device__ float g_k[BH * SEQ * HDIM];
__device__ float g_v[BH * SEQ * HDIM];
__device__ float g_attnout[TOK * DIM];
__device__ float g_x1[TOK * DIM];
__device__ float g_u[TOK * HID];

__device__ __forceinline__ void mma_tf32(float& d0, float& d1, float& d2, float& d3,
                                         unsigned a0, unsigned a1, unsigned a2, unsigned a3,
                                         unsigned b0, unsigned b1)
{
    asm volatile(
        "mma.sync.aligned.m16n8k8.row.col.f32.tf32.tf32.f32 "
        "{%0,%1,%2,%3},{%4,%5,%6,%7},{%8,%9},{%0,%1,%2,%3};"
        : "+f"(d0), "+f"(d1), "+f"(d2), "+f"(d3)
        : "r"(a0), "r"(a1), "r"(a2), "r"(a3), "r"(b0), "r"(b1));
}

__device__ __forceinline__ void ldsm4(unsigned& r0, unsigned& r1, unsigned& r2, unsigned& r3,
                                      unsigned addr)
{
    asm volatile("ldmatrix.sync.aligned.m8n8.x4.shared.b16 {%0,%1,%2,%3}, [%4];"
        : "=r"(r0), "=r"(r1), "=r"(r2), "=r"(r3) : "r"(addr));
}

__device__ __forceinline__ void cp16(unsigned saddr, const void* gptr) {
    asm volatile("cp.async.cg.shared.global [%0], [%1], 16;" :: "r"(saddr), "l"(gptr));
}
#define CP_COMMIT() asm volatile("cp.async.commit_group;")
#define CP_WAIT(n)  asm volatile("cp.async.wait_group %0;" :: "n"(n))
#define BAR_PAIR(id) asm volatile("bar.sync %0, 64;" :: "r"(id) : "memory")

// ============================ LayerNorm: warp-per-row ============================
// 512 threads = 16 warps = 16 rows per block; grid = TOK/16.
__global__ __launch_bounds__(512) void ln_kernel(
    const float* __restrict__ x, const float* __restrict__ gamma,
    const float* __restrict__ beta, float* __restrict__ out)
{
    const int lane = threadIdx.x & 31;
    const int row  = blockIdx.x * 16 + (threadIdx.x >> 5);
    const float* xr = x + (size_t)row * DIM;

    float4 v[6];
    float s = 0.f, s2 = 0.f;
    #pragma unroll
    for (int j = 0; j < 6; j++) {
        v[j] = *(const float4*)(xr + (lane + j * 32) * 4);
        s  += v[j].x + v[j].y + v[j].z + v[j].w;
        s2 += v[j].x * v[j].x + v[j].y * v[j].y + v[j].z * v[j].z + v[j].w * v[j].w;
    }
    #pragma unroll
    for (int o = 16; o; o >>= 1) {
        s  += __shfl_xor_sync(0xffffffffu, s,  o);
        s2 += __shfl_xor_sync(0xffffffffu, s2, o);
    }
    float mean = s * (1.0f / DIM);
    float var  = s2 * (1.0f / DIM) - mean * mean;
    float inv  = rsqrtf(var + LN_EPS);

    float* orow = out + (size_t)row * DIM;
    #pragma unroll
    for (int j = 0; j < 6; j++) {
        int c = (lane + j * 32) * 4;
        float4 g = *(const float4*)(gamma + c);
        float4 b = *(const float4*)(beta + c);
        float4 o;
        o.x = (v[j].x - mean) * inv * g.x + b.x;
        o.y = (v[j].y - mean) * inv * g.y + b.y;
        o.z = (v[j].z - mean) * inv * g.z + b.z;
        o.w = (v[j].w - mean) * inv * g.w + b.w;
        *(float4*)(orow + c) = o;
    }
}

// ============================ TF32 GEMM (round-5 proven): 128x128, k32, 3-stage ============================
#define AS_W 36
#define BS_W 136
#define AS_STAGE (128 * AS_W)
#define BS_STAGE (32 * BS_W)
#define STAGE_W  (AS_STAGE + BS_STAGE)
#define GEMM_SMEM (3 * STAGE_W * 4)

template <int EPI>
__global__ __launch_bounds__(256, 2) void mma_gemm(
    const float* __restrict__ A, const float* __restrict__ W,
    const float* __restrict__ bias, const float* __restrict__ res,
    float* __restrict__ C, int M, int N, int K,
    float* __restrict__ qo, float* __restrict__ ko, float* __restrict__ vo,
    const float* __restrict__ c0, const float* __restrict__ c1,
    const float* __restrict__ c2)
{
    extern __shared__ unsigned smem[];

    const int tid  = threadIdx.x;
    const int lane = tid & 31;
    const int w    = tid >> 5;
    const int wm   = w >> 2;
    const int wn   = w & 3;
    const int bx = blockIdx.x, by = blockIdx.y;

    const int arow = tid >> 3, ac4 = tid & 7;
    const int brow = tid >> 5, bc4 = tid & 31;

    const float* Ag = A + (size_t)(by * 128 + arow) * K + ac4 * 4;
    const float* Bg = W + (size_t)brow * N + bx * 128 + bc4 * 4;

    const unsigned sbase = (unsigned)__cvta_generic_to_shared(smem);
    const int nt = K >> 5;

    #pragma unroll
    for (int t = 0; t < 2; t++) {
        unsigned sb = sbase + t * STAGE_W * 4;
        #pragma unroll
        for (int p = 0; p < 4; p++) {
            cp16(sb + ((arow + p * 32) * AS_W + ac4 * 4) * 4,
                 Ag + (size_t)p * 32 * K + t * 32);
            cp16(sb + (AS_STAGE + (brow + p * 8) * BS_W + bc4 * 4) * 4,
                 Bg + (size_t)(t * 32 + p * 8) * N);
        }
        CP_COMMIT();
    }

    float acc[4][4][4];
    #pragma unroll
    for (int i = 0; i < 4; i++)
        #pragma unroll
        for (int j = 0; j < 4; j++)
            #pragma unroll
            for (int r = 0; r < 4; r++) acc[i][j][r] = 0.f;

    const unsigned a_laneoff = (((lane & 7) + ((lane >> 3) & 1) * 8) * AS_W + (lane >> 4) * 4) * 4;

    int stage = 0;
    for (int t = 0; t < nt; t++) {
        CP_WAIT(1);
        __syncthreads();
        if (t + 2 < nt) {
            int s2 = stage + 2; if (s2 >= 3) s2 -= 3;
            unsigned sb = sbase + s2 * STAGE_W * 4;
            int tt = t + 2;
            #pragma unroll
            for (int p = 0; p < 4; p++) {
                cp16(sb + ((arow + p * 32) * AS_W + ac4 * 4) * 4,
                     Ag + (size_t)p * 32 * K + tt * 32);
                cp16(sb + (AS_STAGE + (brow + p * 8) * BS_W + bc4 * 4) * 4,
                     Bg + (size_t)(tt * 32 + p * 8) * N);
            }
        }
        CP_COMMIT();

        unsigned sA = sbase + stage * STAGE_W * 4;
        const unsigned* BsS = smem + stage * STAGE_W + AS_STAGE;
        #pragma unroll
        for (int kk = 0; kk < 32; kk += 8) {
            unsigned af[4][4], bf[4][2];
            #pragma unroll
            for (int mt = 0; mt < 4; mt++) {
                unsigned addr = sA + ((wm * 64 + mt * 16) * AS_W + kk) * 4 + a_laneoff;
                ldsm4(af[mt][0], af[mt][1], af[mt][2], af[mt][3], addr);
            }
            #pragma unroll
            for (int ntt = 0; ntt < 4; ntt++) {
                int col = wn * 32 + ntt * 8 + (lane >> 2);
                bf[ntt][0] = BsS[(kk + (lane & 3)) * BS_W + col];
                bf[ntt][1] = BsS[(kk + (lane & 3) + 4) * BS_W + col];
            }
            #pragma unroll
            for (int mt = 0; mt < 4; mt++)
                #pragma unroll
                for (int ntt = 0; ntt < 4; ntt++)
                    mma_tf32(acc[mt][ntt][0], acc[mt][ntt][1], acc[mt][ntt][2], acc[mt][ntt][3],
                             af[mt][0], af[mt][1], af[mt][2], af[mt][3],
                             bf[ntt][0], bf[ntt][1]);
        }
        stage++; if (stage == 3) stage = 0;
    }

    float ga = 0.f, gb = 0.f, gc = 0.f;
    if (EPI == 3) { ga = *c0; gb = *c1; gc = *c2; }

    #pragma unroll
    for (int mt = 0; mt < 4; mt++) {
        #pragma unroll
        for (int ntt = 0; ntt < 4; ntt++) {
            int r0  = by * 128 + wm * 64 + mt * 16 + (lane >> 2);
            int cc0 = bx * 128 + wn * 32 + ntt * 8 + 2 * (lane & 3);
            #pragma unroll
            for (int half = 0; half < 2; half++) {
                int r = r0 + half * 8;
                float v0 = acc[mt][ntt][half * 2 + 0] + bias[cc0];
                float v1 = acc[mt][ntt][half * 2 + 1] + bias[cc0 + 1];
                if (EPI == 1) {
                    int which = cc0 / DIM;
                    int jj = cc0 - which * DIM;
                    int h = jj >> 6, d = jj & 63;
                    int b = r >> 11, n = r & 2047;
                    float* dst = (which == 0) ? qo : (which == 1) ? ko : vo;
                    if (which == 0) { v0 *= QKSCALE; v1 *= QKSCALE; }
                    size_t base = (((size_t)(b * NHEAD + h) * SEQ) + n) * HDIM + d;
                    dst[base] = v0; dst[base + 1] = v1;
                } else if (EPI == 2) {
                    size_t base = (size_t)r * N + cc0;
                    C[base]     = v0 + res[base];
                    C[base + 1] = v1 + res[base + 1];
                } else if (EPI == 3) {
                    size_t base = (size_t)r * N + cc0;
                    C[base]     = fmaf(v0, fmaf(ga, v0, gb), gc);
                    C[base + 1] = fmaf(v1, fmaf(ga, v1, gb), gc);
                } else {
                    size_t base = (size_t)r * N + cc0;
                    C[base] = v0; C[base + 1] = v1;
                }
            }
        }
    }
}

// ============================ Polynomial attention (round-5 proven) ============================
#define KS_W 68
#define VS_W 72
#define KS_T (64 * KS_W)
#define VS_T (64 * VS_W)
#define ATTN_SMEM ((2 * KS_T + 2 * VS_T + 64 * 68) * 4)

__global__ __launch_bounds__(256, 2) void attn_mma(
    const float* __restrict__ Q, const float* __restrict__ Kg,
    const float* __restrict__ Vg, float* __restrict__ out,
    const float* __restrict__ pa, const float* __restrict__ pb,
    const float* __restrict__ pc)
{
    extern __shared__ unsigned dsm[];
    unsigned* Ks = dsm;
    unsigned* Vs = dsm + 2 * KS_T;
    unsigned* Ss = dsm + 2 * KS_T + 2 * VS_T;
    __shared__ float rsums[64];

    const int tid  = threadIdx.x;
    const int lane = tid & 31;
    const int w    = tid >> 5;
    const int mt   = w >> 1;
    const int nh   = w & 1;
    const int bh   = blockIdx.y;
    const int n0   = blockIdx.x * 64;

    const float* Qb = Q  + (size_t)bh * SEQ * HDIM;
    const float* Kb = Kg + (size_t)bh * SEQ * HDIM;
    const float* Vb = Vg + (size_t)bh * SEQ * HDIM;

    const float aa = *pa, bb = *pb, cc = *pc;

    if (tid < 64) rsums[tid] = 0.f;

    const int grow = tid >> 4;
    const int gc4  = tid & 15;

    const unsigned sKs = (unsigned)__cvta_generic_to_shared(Ks);
    const unsigned sVs = (unsigned)__cvta_generic_to_shared(Vs);
    const unsigned sSs = (unsigned)__cvta_generic_to_shared(Ss);

    #pragma unroll
    for (int it = 0; it < 4; it++) {
        int r = it * 16 + grow;
        cp16(sSs + (r * 68 + gc4 * 4) * 4, Qb + (size_t)(n0 + r) * HDIM + gc4 * 4);
    }
    CP_COMMIT();
    #pragma unroll
    for (int t = 0; t < 2; t++) {
        #pragma unroll
        for (int it = 0; it < 4; it++) {
            int r = it * 16 + grow;
            cp16(sKs + (t * KS_T + r * KS_W + gc4 * 4) * 4,
                 Kb + (size_t)(t * 64 + r) * HDIM + gc4 * 4);
            cp16(sVs + (t * VS_T + r * VS_W + gc4 * 4) * 4,
                 Vb + (size_t)(t * 64 + r) * HDIM + gc4 * 4);
        }
        CP_COMMIT();
    }
    CP_WAIT(2);
    __syncthreads();

    const unsigned a_laneoff = (((lane & 7) + ((lane >> 3) & 1) * 8) * 68 + (lane >> 4) * 4) * 4;
    const unsigned b_laneoff = (((lane & 7) + ((lane >> 4) & 1) * 8) * KS_W + ((lane >> 3) & 1) * 4) * 4;

    unsigned qf[8][4];
    #pragma unroll
    for (int kk = 0; kk < 8; kk++) {
        unsigned addr = sSs + (mt * 16 * 68 + kk * 8) * 4 + a_laneoff;
        ldsm4(qf[kk][0], qf[kk][1], qf[kk][2], qf[kk][3], addr);
    }

    float oacc[4][4];
    #pragma unroll
    for (int ntt = 0; ntt < 4; ntt++)
        #pragma unroll
        for (int r = 0; r < 4; r++) oacc[ntt][r] = 0.f;
    float rs0 = 0.f, rs1 = 0.f;

    for (int m = 0; m < 32; m++) {
        const int buf = m & 1;
        CP_WAIT(1);
        __syncthreads();

        float sacc[4][4];
        #pragma unroll
        for (int ntt = 0; ntt < 4; ntt++)
            #pragma unroll
            for (int r = 0; r < 4; r++) sacc[ntt][r] = 0.f;

        unsigned kbase = sKs + buf * KS_T * 4;
        #pragma unroll
        for (int kk = 0; kk < 8; kk++) {
            unsigned bf[4][2];
            #pragma unroll
            for (int p = 0; p < 2; p++) {
                unsigned addr = kbase + ((nh * 32 + p * 16) * KS_W + kk * 8) * 4 + b_laneoff;
                ldsm4(bf[2 * p][0], bf[2 * p][1], bf[2 * p + 1][0], bf[2 * p + 1][1], addr);
            }
            #pragma unroll
            for (int ntt = 0; ntt < 4; ntt++)
                mma_tf32(sacc[ntt][0], sacc[ntt][1], sacc[ntt][2], sacc[ntt][3],
                         qf[kk][0], qf[kk][1], qf[kk][2], qf[kk][3],
                         bf[ntt][0], bf[ntt][1]);
        }

        #pragma unroll
        for (int ntt = 0; ntt < 4; ntt++) {
            #pragma unroll
            for (int r = 0; r < 4; r++) {
                float t = sacc[ntt][r];
                t = fmaf(t, fmaf(aa, t, bb), cc);
                t = fmaxf(t, 1e-6f);
                sacc[ntt][r] = t;
                if (r < 2) rs0 += t; else rs1 += t;
            }
        }

        #pragma unroll
        for (int ntt = 0; ntt < 4; ntt++) {
            int row = mt * 16 + (lane >> 2);
            int col = nh * 32 + ntt * 8 + 2 * (lane & 3);
            uint2 u0 = make_uint2(__float_as_uint(sacc[ntt][0]), __float_as_uint(sacc[ntt][1]));
            uint2 u1 = make_uint2(__float_as_uint(sacc[ntt][2]), __float_as_uint(sacc[ntt][3]));
            *(uint2*)&Ss[row * 68 + col]       = u0;
            *(uint2*)&Ss[(row + 8) * 68 + col] = u1;
        }
        BAR_PAIR(1 + mt);

        const unsigned* Vbuf = Vs + buf * VS_T;
        #pragma unroll
        for (int kk = 0; kk < 8; kk++) {
            unsigned af[4];
            unsigned addr = sSs + (mt * 16 * 68 + kk * 8) * 4 + a_laneoff;
            ldsm4(af[0], af[1], af[2], af[3], addr);
            unsigned bfv[4][2];
            #pragma unroll
            for (int ntt = 0; ntt < 4; ntt++) {
                int dcol = nh * 32 + ntt * 8 + (lane >> 2);
                bfv[ntt][0] = Vbuf[(kk * 8 + (lane & 3)) * VS_W + dcol];
                bfv[ntt][1] = Vbuf[(kk * 8 + (lane & 3) + 4) * VS_W + dcol];
            }
            #pragma unroll
            for (int ntt = 0; ntt < 4; ntt++)
                mma_tf32(oacc[ntt][0], oacc[ntt][1], oacc[ntt][2], oacc[ntt][3],
                         af[0], af[1], af[2], af[3],
                         bfv[ntt][0], bfv[ntt][1]);
        }
        __syncthreads();

        if (m + 2 < 32) {
            int tt = m + 2;
            #pragma unroll
            for (int it = 0; it < 4; it++) {
                int r = it * 16 + grow;
                cp16(sKs + (buf * KS_T + r * KS_W + gc4 * 4) * 4,
                     Kb + (size_t)(tt * 64 + r) * HDIM + gc4 * 4);
                cp16(sVs + (buf * VS_T + r * VS_W + gc4 * 4) * 4,
                     Vb + (size_t)(tt * 64 + r) * HDIM + gc4 * 4);
            }
        }
        CP_COMMIT();
    }

    rs0 += __shfl_xor_sync(0xffffffffu, rs0, 1);
    rs0 += __shfl_xor_sync(0xffffffffu, rs0, 2);
    rs1 += __shfl_xor_sync(0xffffffffu, rs1, 1);
    rs1 += __shfl_xor_sync(0xffffffffu, rs1, 2);
    if ((lane & 3) == 0) {
        atomicAdd(&rsums[mt * 16 + (lane >> 2)], rs0);
        atomicAdd(&rsums[mt * 16 + (lane >> 2) + 8], rs1);
    }
    __syncthreads();

    int b = bh / NHEAD, h = bh % NHEAD;
    int row0 = mt * 16 + (lane >> 2);
    float inv0 = 1.0f / (rsums[row0] + 1e-8f);
    float inv1 = 1.0f / (rsums[row0 + 8] + 1e-8f);
    #pragma unroll
    for (int ntt = 0; ntt < 4; ntt++) {
        int d = nh * 32 + ntt * 8 + 2 * (lane & 3);
        size_t base0 = ((size_t)(b * SEQ + n0 + row0)) * DIM + h * HDIM + d;
        size_t base1 = ((size_t)(b * SEQ + n0 + row0 + 8)) * DIM + h * HDIM + d;
        out[base0]     = oacc[ntt][0] * inv0;
        out[base0 + 1] = oacc[ntt][1] * inv0;
        out[base1]     = oacc[ntt][2] * inv1;
        out[base1 + 1] = oacc[ntt][3] * inv1;
    }
}

// ============================ launch ============================
extern "C" void kernel_launch(void* const* d_in, const int* in_sizes, int n_in,
                              void* d_out, int out_size)
{
    const float* x      = (const float*)d_in[0];
    const float* ln1_g  = (const float*)d_in[1];
    const float* ln1_b  = (const float*)d_in[2];
    const float* ln2_g  = (const float*)d_in[3];
    const float* ln2_b  = (const float*)d_in[4];
    const float* qkv_w  = (const float*)d_in[5];
    const float* qkv_b  = (const float*)d_in[6];
    const float* proj_w = (const float*)d_in[7];
    const float* proj_b = (const float*)d_in[8];
    const float* fc1_w  = (const float*)d_in[9];
    const float* fc1_b  = (const float*)d_in[10];
    const float* fc2_w  = (const float*)d_in[11];
    const float* fc2_b  = (const float*)d_in[12];
    const float* attn_a = (const float*)d_in[13];
    const float* attn_b = (const float*)d_in[14];
    const float* attn_c = (const float*)d_in[15];
    const float* gelu_a = (const float*)d_in[16];
    const float* gelu_b = (const float*)d_in[17];
    const float* gelu_c = (const float*)d_in[18];
    float* out = (float*)d_out;

    void *p_h, *p_q, *p_k, *p_v, *p_ao, *p_x1, *p_u;
    cudaGetSymbolAddress(&p_h,  g_h);
    cudaGetSymbolAddress(&p_q,  g_q);
    cudaGetSymbolAddress(&p_k,  g_k);
    cudaGetSymbolAddress(&p_v,  g_v);
    cudaGetSymbolAddress(&p_ao, g_attnout);
    cudaGetSymbolAddress(&p_x1, g_x1);
    cudaGetSymbolAddress(&p_u,  g_u);
    float* h_  = (float*)p_h;
    float* q_  = (float*)p_q;
    float* k_  = (float*)p_k;
    float* v_  = (float*)p_v;
    float* ao_ = (float*)p_ao;
    float* x1_ = (float*)p_x1;
    float* u_  = (float*)p_u;

    static int attr_set = 0;
    if (!attr_set) {
        cudaFuncSetAttribute(attn_mma, cudaFuncAttributeMaxDynamicSharedMemorySize, ATTN_SMEM);
        cudaFuncSetAttribute(mma_gemm<1>, cudaFuncAttributeMaxDynamicSharedMemorySize, GEMM_SMEM);
        cudaFuncSetAttribute(mma_gemm<2>, cudaFuncAttributeMaxDynamicSharedMemorySize, GEMM_SMEM);
        cudaFuncSetAttribute(mma_gemm<3>, cudaFuncAttributeMaxDynamicSharedMemorySize, GEMM_SMEM);
        attr_set = 1;
    }

    ln_kernel<<<TOK / 16, 512>>>(x, ln1_g, ln1_b, h_);
    mma_gemm<1><<<dim3(3 * DIM / 128, TOK / 128), 256, GEMM_SMEM>>>(
        h_, qkv_w, qkv_b, nullptr, nullptr, TOK, 3 * DIM, DIM,
        q_, k_, v_, nullptr, nullptr, nullptr);
    attn_mma<<<dim3(SEQ / 64, BH), 256, ATTN_SMEM>>>(q_, k_, v_, ao_,
                                                     attn_a, attn_b, attn_c);
    mma_gemm<2><<<dim3(DIM / 128, TOK / 128), 256, GEMM_SMEM>>>(
        ao_, proj_w, proj_b, x, x1_, TOK, DIM, DIM,
        nullptr, nullptr, nullptr, nullptr, nullptr, nullptr);
    ln_kernel<<<TOK / 16, 512>>>(x1_, ln2_g, ln2_b, h_);
    mma_gemm<3><<<dim3(HID / 128, TOK / 128), 256, GEMM_SMEM>>>(
        h_, fc1_w, fc1_b, nullptr, u_, TOK, HID, DIM,
        nullptr, nullptr, nullptr, gelu_a, gelu_b, gelu_c);
    mma_gemm<2><<<dim3(DIM / 128, TOK / 128), 256, GEMM_SMEM>>>(
        u_, fc2_w, fc2_b, x1_, out, TOK, DIM, HID,
        nullptr, nullptr, nullptr, nullptr, nullptr, nullptr);
}